// round 16
// baseline (speedup 1.0000x reference)
#include <cuda_runtime.h>
#include <cuda_fp16.h>
#include <cstdint>

// ---------------------------------------------------------------------------
// y[b,s,o] = sum_i x[b,s,i]*w[o,i] + bias[o],  w = (q-128)*scale (Q8_0)
// dtypes: x f32 [4,1024,4096], q i32 [4096,128,32], scales f32, bias f32
// -> out f32.  GEMM: A=x [M,K] f16, B=w [N,K] f16 (col-major for row.col),
// C [M,N] f32.  compute_103: no tcgen05 -> mma.sync + cp.async.
// R16: persistent 296 CTAs x tile 128x64 (2048 tiles -> wave-quant loss
// 13.5% -> 1.2%) with the R15 mbarrier full/empty pipeline streaming
// cp.async stages SEAMLESSLY across tile boundaries (no drain/re-prologue).
// ---------------------------------------------------------------------------

#define MAX_O 4096
#define MAX_K 4096
#define MAX_M 4096

__device__ __half g_w[(size_t)MAX_O * MAX_K];  // dequantized weights [N,K]
__device__ __half g_x[(size_t)MAX_M * MAX_K];  // f16 activations    [M,K]

// ---------------------------------------------------------------------------
// Merged prep: x f32->f16 and q i32->f16 dequant in one launch.
// ---------------------------------------------------------------------------
__global__ void prep_kernel(const float* __restrict__ x,
                            const int* __restrict__ q,
                            const float* __restrict__ scales,
                            int nx_chunks, int O, int K) {
    int idx = blockIdx.x * blockDim.x + threadIdx.x;
    if (idx < nx_chunks) {
        size_t i = (size_t)idx * 8;
        const float4* xp = reinterpret_cast<const float4*>(x + i);
        float4 a = xp[0], b = xp[1];
        __half h[8];
        h[0] = __float2half(a.x); h[1] = __float2half(a.y);
        h[2] = __float2half(a.z); h[3] = __float2half(a.w);
        h[4] = __float2half(b.x); h[5] = __float2half(b.y);
        h[6] = __float2half(b.z); h[7] = __float2half(b.w);
        *reinterpret_cast<float4*>(&g_x[i]) = *reinterpret_cast<const float4*>(h);
        return;
    }
    int c = idx - nx_chunks;
    int chunks_per_row = K >> 3;
    if (c >= O * chunks_per_row) return;
    int o  = c / chunks_per_row;
    int k0 = (c - o * chunks_per_row) << 3;
    int nb = k0 >> 5;
    float s = scales[o * (K >> 5) + nb];

    const int4* qp = reinterpret_cast<const int4*>(q + (size_t)o * K + k0);
    int4 q0 = qp[0];
    int4 q1 = qp[1];

    __half h[8];
    h[0] = __float2half((float)(q0.x - 128) * s);
    h[1] = __float2half((float)(q0.y - 128) * s);
    h[2] = __float2half((float)(q0.z - 128) * s);
    h[3] = __float2half((float)(q0.w - 128) * s);
    h[4] = __float2half((float)(q1.x - 128) * s);
    h[5] = __float2half((float)(q1.y - 128) * s);
    h[6] = __float2half((float)(q1.z - 128) * s);
    h[7] = __float2half((float)(q1.w - 128) * s);

    *reinterpret_cast<float4*>(&g_w[(size_t)o * K + k0]) =
        *reinterpret_cast<const float4*>(h);
}

// ---------------------------------------------------------------------------
// GEMM: persistent, mma.sync m16n8k16, tile 128x64x64, 4 warps (2x2) of
// 64x32 warp tiles, 3-stage mbarrier cp.async pipeline streaming across
// tiles, SW128 smem, raster tile order, 2 CTA/SM.
// ---------------------------------------------------------------------------
constexpr int BM = 128, BN = 64, BK = 64;
constexpr int THREADS = 128;
constexpr int STAGES = 3;

constexpr int A_BYTES = BM * 128;                 // 16 KB
constexpr int B_BYTES = BN * 128;                 // 8 KB
constexpr int STAGE_BYTES = A_BYTES + B_BYTES;    // 24 KB
constexpr int SM_MBAR  = 0;                       // full[3]@0,8,16; empty[3]@24,32,40
constexpr int SM_TILES = 1024;
constexpr int SMEM_TOTAL = SM_TILES + STAGES * STAGE_BYTES;  // ~73 KB

constexpr int PERSISTENT_CTAS = 296;              // 2 per SM x 148

__device__ __forceinline__ uint32_t smem_u32(const void* p) {
    uint32_t a;
    asm("{ .reg .u64 t; cvta.to.shared.u64 t, %1; cvt.u32.u64 %0, t; }"
        : "=r"(a) : "l"(p));
    return a;
}
__device__ __forceinline__ uint32_t sw128(uint32_t off) {
    return off ^ ((off >> 3) & 0x70);
}
__device__ __forceinline__ void cp16(uint32_t saddr, const void* gaddr) {
    asm volatile("cp.async.cg.shared.global [%0], [%1], 16;"
                 :: "r"(saddr), "l"(gaddr));
}
__device__ __forceinline__ void mbar_init(uint32_t addr, uint32_t cnt) {
    asm volatile("mbarrier.init.shared.b64 [%0], %1;"
                 :: "r"(addr), "r"(cnt) : "memory");
}
__device__ __forceinline__ void mbar_arrive(uint32_t addr) {
    asm volatile("mbarrier.arrive.shared.b64 _, [%0];" :: "r"(addr) : "memory");
}
__device__ __forceinline__ void cp_arrive_noinc(uint32_t addr) {
    asm volatile("cp.async.mbarrier.arrive.noinc.shared.b64 [%0];"
                 :: "r"(addr) : "memory");
}
__device__ __forceinline__ void mbar_wait(uint32_t addr, uint32_t parity) {
    asm volatile(
        "{\n\t"
        ".reg .pred P;\n\t"
        "LAB_W_%=:\n\t"
        "mbarrier.try_wait.parity.acquire.cta.shared::cta.b64 P, [%0], %1, 0x989680;\n\t"
        "@P bra LAB_D_%=;\n\t"
        "bra LAB_W_%=;\n\t"
        "LAB_D_%=:\n\t"
        "}"
        :: "r"(addr), "r"(parity) : "memory");
}
__device__ __forceinline__ void ldmx4(uint32_t* r, uint32_t addr) {
    asm volatile("ldmatrix.sync.aligned.m8n8.x4.shared.b16 {%0,%1,%2,%3}, [%4];"
                 : "=r"(r[0]), "=r"(r[1]), "=r"(r[2]), "=r"(r[3]) : "r"(addr));
}
__device__ __forceinline__ void mma16816(float* c, const uint32_t* a,
                                         const uint32_t* b) {
    asm volatile(
        "mma.sync.aligned.m16n8k16.row.col.f32.f16.f16.f32 "
        "{%0,%1,%2,%3}, {%4,%5,%6,%7}, {%8,%9}, {%0,%1,%2,%3};"
        : "+f"(c[0]), "+f"(c[1]), "+f"(c[2]), "+f"(c[3])
        : "r"(a[0]), "r"(a[1]), "r"(a[2]), "r"(a[3]), "r"(b[0]), "r"(b[1]));
}

__global__ void __launch_bounds__(THREADS, 2)
gemm_mma_kernel(const float* __restrict__ bias,
                float* __restrict__ C, int M, int N, int K) {
    extern __shared__ char smem[];
    const uint32_t sb       = smem_u32(smem);
    const uint32_t sb_tiles = sb + SM_TILES;
    const int tid  = threadIdx.x;
    const int wid  = tid >> 5;
    const int lane = tid & 31;

    const int nbx = N / BN;               // 64
    const int nby = M / BM;               // 32
    const int ntiles = nbx * nby;         // 2048

    const int wm_off = (wid >> 1) * 64;   // 0 or 64
    const int wn_off = (wid & 1) * 32;    // 0 or 32

    if (tid == 0) {
#pragma unroll
        for (int s = 0; s < STAGES; s++) {
            mbar_init(sb + SM_MBAR + s * 8, THREADS);        // full
            mbar_init(sb + SM_MBAR + 24 + s * 8, THREADS);   // empty
        }
    }
    __syncthreads();

    // Raster: GROUP M-tiles per N-column sweep (L2 reuse across co-running CTAs)
    constexpr int GROUP = 16;
    auto tile_coords = [&](int t, int& tbm, int& tbn) {
        int tiles_per_group = GROUP * nbx;
        int g   = t / tiles_per_group;
        int rem = t - g * tiles_per_group;
        int gm  = g * GROUP;
        int gsz = (nby - gm) < GROUP ? (nby - gm) : GROUP;
        tbm = (gm + rem % gsz) * BM;
        tbn = (rem / gsz) * BN;
    };

    const int lr = tid >> 3;        // base row 0..15 (stride 16)
    const int lc = (tid & 7) * 8;   // element offset within 64-wide k-row

    // ---- producer state: streams fills across tile boundaries ----
    int p_tile = blockIdx.x;
    int p_kblk = 0;
    const __half *Agp = nullptr, *Bgp = nullptr;
    {
        int tbm, tbn;
        tile_coords(p_tile, tbm, tbn);
        Agp = g_x + (size_t)tbm * K;
        Bgp = g_w + (size_t)tbn * K;
    }
    int p_stage = 0, p_phase = 1;   // empty-waits pass on first cycle

    auto fill_advance = [&]() {
        mbar_wait(sb + SM_MBAR + 24 + p_stage * 8, p_phase);
        uint32_t a_s = sb_tiles + p_stage * STAGE_BYTES;
        uint32_t b_s = a_s + A_BYTES;
#pragma unroll
        for (int i = 0; i < 8; i++) {                 // A: 128 rows
            int r = lr + i * 16;
            cp16(a_s + sw128(r * 128 + lc * 2), Agp + (size_t)r * K + p_kblk + lc);
        }
#pragma unroll
        for (int i = 0; i < 4; i++) {                 // B: 64 rows
            int r = lr + i * 16;
            cp16(b_s + sw128(r * 128 + lc * 2), Bgp + (size_t)r * K + p_kblk + lc);
        }
        cp_arrive_noinc(sb + SM_MBAR + p_stage * 8);
        if (++p_stage == STAGES) { p_stage = 0; p_phase ^= 1; }
        p_kblk += BK;
        if (p_kblk == K) {
            p_kblk = 0;
            p_tile += gridDim.x;
            if (p_tile < ntiles) {
                int tbm, tbn;
                tile_coords(p_tile, tbm, tbn);
                Agp = g_x + (size_t)tbm * K;
                Bgp = g_w + (size_t)tbn * K;
            }
        }
    };

    // Prologue: 2 fills ahead
    fill_advance();
    fill_advance();

    int c_stage = 0, c_phase = 0;
    const int iters = K / BK;     // 64

    // ldmatrix lane addressing
    const int a_row_l = lane & 15;
    const int a_chk_l = lane >> 4;
    const int b_row_l = (lane & 7) + ((lane >> 4) << 3);
    const int b_chk_l = (lane >> 3) & 1;

    float acc[4][4][4];
#pragma unroll
    for (int mi = 0; mi < 4; mi++)
#pragma unroll
        for (int ni = 0; ni < 4; ni++)
#pragma unroll
            for (int e = 0; e < 4; e++) acc[mi][ni][e] = 0.0f;

    uint32_t afrag[2][4][4];
    uint32_t bfrag[2][2][4];

    for (int t = blockIdx.x; t < ntiles; t += gridDim.x) {
        int bm, bn;
        tile_coords(t, bm, bn);

        for (int it = 0; it < iters; ++it) {
            mbar_wait(sb + SM_MBAR + c_stage * 8, c_phase);   // full[cur]

            uint32_t a_s = sb_tiles + c_stage * STAGE_BYTES;
            uint32_t b_s = a_s + A_BYTES;

            // Prefetch ks=0 fragments
#pragma unroll
            for (int mi = 0; mi < 4; mi++) {
                int row = wm_off + mi * 16 + a_row_l;
                ldmx4(afrag[0][mi], a_s + sw128(row * 128 + a_chk_l * 16));
            }
#pragma unroll
            for (int nj = 0; nj < 2; nj++) {
                int row = wn_off + nj * 16 + b_row_l;
                ldmx4(bfrag[0][nj], b_s + sw128(row * 128 + b_chk_l * 16));
            }

#pragma unroll
            for (int ks = 0; ks < BK / 16; ks++) {
                const int cur = ks & 1;
                if (ks < BK / 16 - 1) {
                    const int nxt = cur ^ 1;
#pragma unroll
                    for (int mi = 0; mi < 4; mi++) {
                        int row = wm_off + mi * 16 + a_row_l;
                        ldmx4(afrag[nxt][mi],
                              a_s + sw128(row * 128 + (ks + 1) * 32 + a_chk_l * 16));
                    }
#pragma unroll
                    for (int nj = 0; nj < 2; nj++) {
                        int row = wn_off + nj * 16 + b_row_l;
                        ldmx4(bfrag[nxt][nj],
                              b_s + sw128(row * 128 + (ks + 1) * 32 + b_chk_l * 16));
                    }
                }
#pragma unroll
                for (int mi = 0; mi < 4; mi++)
#pragma unroll
                    for (int ni = 0; ni < 4; ni++)
                        mma16816(acc[mi][ni], afrag[cur][mi],
                                 &bfrag[cur][ni >> 1][(ni & 1) * 2]);
            }

            // Release stage, then keep the producer 2 ahead (streams into
            // the next tile seamlessly).
            mbar_arrive(sb + SM_MBAR + 24 + c_stage * 8);
            if (++c_stage == STAGES) { c_stage = 0; c_phase ^= 1; }

            if (p_tile < ntiles)
                fill_advance();
        }

        // Epilogue: registers -> global, bias via __ldg, float2 stores.
        // Producer cp.asyncs for the next tile remain in flight meanwhile.
#pragma unroll
        for (int mi = 0; mi < 4; mi++) {
            int r0 = bm + wm_off + mi * 16 + (lane >> 2);
#pragma unroll
            for (int ni = 0; ni < 4; ni++) {
                int col  = wn_off + ni * 8 + (lane & 3) * 2;
                float b0 = __ldg(&bias[bn + col]);
                float b1 = __ldg(&bias[bn + col + 1]);
                float2 v0 = make_float2(acc[mi][ni][0] + b0, acc[mi][ni][1] + b1);
                float2 v1 = make_float2(acc[mi][ni][2] + b0, acc[mi][ni][3] + b1);
                *reinterpret_cast<float2*>(C + (size_t)r0 * N + bn + col) = v0;
                *reinterpret_cast<float2*>(C + (size_t)(r0 + 8) * N + bn + col) = v1;
                acc[mi][ni][0] = 0.0f; acc[mi][ni][1] = 0.0f;
                acc[mi][ni][2] = 0.0f; acc[mi][ni][3] = 0.0f;
            }
        }
    }
}

// ---------------------------------------------------------------------------
// Launch
// ---------------------------------------------------------------------------
extern "C" void kernel_launch(void* const* d_in, const int* in_sizes, int n_in,
                              void* d_out, int out_size) {
    const float* x      = (const float*)d_in[0];
    const int*   q      = (const int*)  d_in[1];
    const float* scales = (const float*)d_in[2];
    const float* bias   = (const float*)d_in[3];
    float*       out    = (float*)d_out;

    const int O = in_sizes[3];                 // 4096
    const int K = in_sizes[1] / O;             // 4096
    const int M = in_sizes[0] / K;             // 4096
    const int N = O;

    int nx_chunks = (int)((size_t)M * K / 8);
    int nq_chunks = O * (K >> 3);
    int total = nx_chunks + nq_chunks;
    prep_kernel<<<(total + 255) / 256, 256>>>(x, q, scales, nx_chunks, O, K);

    cudaFuncSetAttribute(gemm_mma_kernel,
                         cudaFuncAttributeMaxDynamicSharedMemorySize, SMEM_TOTAL);
    gemm_mma_kernel<<<PERSISTENT_CTAS, THREADS, SMEM_TOTAL>>>(bias, out, M, N, K);
}

// round 17
// speedup vs baseline: 1.0714x; 1.0714x over previous
#include <cuda_runtime.h>
#include <cuda_fp16.h>
#include <cstdint>

// ---------------------------------------------------------------------------
// y[b,s,o] = sum_i x[b,s,i]*w[o,i] + bias[o],  w = (q-128)*scale (Q8_0)
// dtypes: x f32 [4,1024,4096], q i32 [4096,128,32], scales f32, bias f32
// -> out f32.  GEMM: A=x [M,K] f16, B=w [N,K] f16, C [M,N] f32.
// compute_103: no tcgen05 -> mma.sync + cp.async.
// R17: R15 champion mainloop (128x128x64, 4 warps 64x64, 3-stage mbarrier
// pipeline, 2 CTA/SM) + TAIL-BALANCED SPLIT-K: 888 full-K jobs (3 exact
// waves of 296) + 136 tiles split into 272 half-K jobs that backfill the
// ragged 4th wave -> wave-quantization loss 13.5% -> ~1.2%. Split partials
// go to a device buffer; a small reduce kernel sums them into C.
// ---------------------------------------------------------------------------

#define MAX_O 4096
#define MAX_K 4096
#define MAX_M 4096

__device__ __half g_w[(size_t)MAX_O * MAX_K];  // dequantized weights [N,K]
__device__ __half g_x[(size_t)MAX_M * MAX_K];  // f16 activations    [M,K]

constexpr int SLOTS      = 296;                // 2 CTA/SM x 148 SMs
constexpr int MAX_NSPLIT = 160;                // >= actual 136
__device__ float g_part[(size_t)MAX_NSPLIT * 2 * 128 * 128];  // ~21 MB

// ---------------------------------------------------------------------------
// Merged prep: x f32->f16 and q i32->f16 dequant in one launch.
// ---------------------------------------------------------------------------
__global__ void prep_kernel(const float* __restrict__ x,
                            const int* __restrict__ q,
                            const float* __restrict__ scales,
                            int nx_chunks, int O, int K) {
    int idx = blockIdx.x * blockDim.x + threadIdx.x;
    if (idx < nx_chunks) {
        size_t i = (size_t)idx * 8;
        const float4* xp = reinterpret_cast<const float4*>(x + i);
        float4 a = xp[0], b = xp[1];
        __half h[8];
        h[0] = __float2half(a.x); h[1] = __float2half(a.y);
        h[2] = __float2half(a.z); h[3] = __float2half(a.w);
        h[4] = __float2half(b.x); h[5] = __float2half(b.y);
        h[6] = __float2half(b.z); h[7] = __float2half(b.w);
        *reinterpret_cast<float4*>(&g_x[i]) = *reinterpret_cast<const float4*>(h);
        return;
    }
    int c = idx - nx_chunks;
    int chunks_per_row = K >> 3;
    if (c >= O * chunks_per_row) return;
    int o  = c / chunks_per_row;
    int k0 = (c - o * chunks_per_row) << 3;
    int nb = k0 >> 5;
    float s = scales[o * (K >> 5) + nb];

    const int4* qp = reinterpret_cast<const int4*>(q + (size_t)o * K + k0);
    int4 q0 = qp[0];
    int4 q1 = qp[1];

    __half h[8];
    h[0] = __float2half((float)(q0.x - 128) * s);
    h[1] = __float2half((float)(q0.y - 128) * s);
    h[2] = __float2half((float)(q0.z - 128) * s);
    h[3] = __float2half((float)(q0.w - 128) * s);
    h[4] = __float2half((float)(q1.x - 128) * s);
    h[5] = __float2half((float)(q1.y - 128) * s);
    h[6] = __float2half((float)(q1.z - 128) * s);
    h[7] = __float2half((float)(q1.w - 128) * s);

    *reinterpret_cast<float4*>(&g_w[(size_t)o * K + k0]) =
        *reinterpret_cast<const float4*>(h);
}

// ---------------------------------------------------------------------------
// Shared tile rasterization (GROUP M-tiles per N sweep)
// ---------------------------------------------------------------------------
__device__ __forceinline__ void tile_coords(int t, int nbx, int nby,
                                            int& tbm, int& tbn) {
    constexpr int GROUP = 16;
    int tiles_per_group = GROUP * nbx;
    int g   = t / tiles_per_group;
    int rem = t - g * tiles_per_group;
    int gm  = g * GROUP;
    int gsz = (nby - gm) < GROUP ? (nby - gm) : GROUP;
    tbm = (gm + rem % gsz);
    tbn = (rem / gsz);
}

// ---------------------------------------------------------------------------
// GEMM: mma.sync m16n8k16, tile 128x128x64, 4 warps (2x2) of 64x64,
// 3-stage mbarrier cp.async pipeline, SW128 smem. Jobs: full-K or half-K.
// ---------------------------------------------------------------------------
constexpr int BM = 128, BN = 128, BK = 64;
constexpr int THREADS = 128;
constexpr int STAGES = 3;

constexpr int TILE_BYTES  = BM * 128;             // 16 KB each (A and B)
constexpr int STAGE_BYTES = 2 * TILE_BYTES;       // 32 KB
constexpr int SM_MBAR  = 0;                       // full[3]@0..16; empty[3]@24..40
constexpr int SM_TILES = 1024;
constexpr int SMEM_TOTAL = SM_TILES + STAGES * STAGE_BYTES;  // 97.5 KB

__device__ __forceinline__ uint32_t smem_u32(const void* p) {
    uint32_t a;
    asm("{ .reg .u64 t; cvta.to.shared.u64 t, %1; cvt.u32.u64 %0, t; }"
        : "=r"(a) : "l"(p));
    return a;
}
__device__ __forceinline__ uint32_t sw128(uint32_t off) {
    return off ^ ((off >> 3) & 0x70);
}
__device__ __forceinline__ void cp16(uint32_t saddr, const void* gaddr) {
    asm volatile("cp.async.cg.shared.global [%0], [%1], 16;"
                 :: "r"(saddr), "l"(gaddr));
}
__device__ __forceinline__ void mbar_init(uint32_t addr, uint32_t cnt) {
    asm volatile("mbarrier.init.shared.b64 [%0], %1;"
                 :: "r"(addr), "r"(cnt) : "memory");
}
__device__ __forceinline__ void mbar_arrive(uint32_t addr) {
    asm volatile("mbarrier.arrive.shared.b64 _, [%0];" :: "r"(addr) : "memory");
}
__device__ __forceinline__ void cp_arrive_noinc(uint32_t addr) {
    asm volatile("cp.async.mbarrier.arrive.noinc.shared.b64 [%0];"
                 :: "r"(addr) : "memory");
}
__device__ __forceinline__ void mbar_wait(uint32_t addr, uint32_t parity) {
    asm volatile(
        "{\n\t"
        ".reg .pred P;\n\t"
        "LAB_W_%=:\n\t"
        "mbarrier.try_wait.parity.acquire.cta.shared::cta.b64 P, [%0], %1, 0x989680;\n\t"
        "@P bra LAB_D_%=;\n\t"
        "bra LAB_W_%=;\n\t"
        "LAB_D_%=:\n\t"
        "}"
        :: "r"(addr), "r"(parity) : "memory");
}
__device__ __forceinline__ void ldmx4(uint32_t* r, uint32_t addr) {
    asm volatile("ldmatrix.sync.aligned.m8n8.x4.shared.b16 {%0,%1,%2,%3}, [%4];"
                 : "=r"(r[0]), "=r"(r[1]), "=r"(r[2]), "=r"(r[3]) : "r"(addr));
}
__device__ __forceinline__ void mma16816(float* c, const uint32_t* a,
                                         const uint32_t* b) {
    asm volatile(
        "mma.sync.aligned.m16n8k16.row.col.f32.f16.f16.f32 "
        "{%0,%1,%2,%3}, {%4,%5,%6,%7}, {%8,%9}, {%0,%1,%2,%3};"
        : "+f"(c[0]), "+f"(c[1]), "+f"(c[2]), "+f"(c[3])
        : "r"(a[0]), "r"(a[1]), "r"(a[2]), "r"(a[3]), "r"(b[0]), "r"(b[1]));
}

__global__ void __launch_bounds__(THREADS, 2)
gemm_mma_kernel(const float* __restrict__ bias,
                float* __restrict__ C, int M, int N, int K,
                int full_jobs, int ntiles) {
    extern __shared__ char smem[];
    const uint32_t sb       = smem_u32(smem);
    const uint32_t sb_tiles = sb + SM_TILES;
    const int tid  = threadIdx.x;
    const int wid  = tid >> 5;
    const int lane = tid & 31;

    const int nbx = N / BN;
    const int nby = M / BM;

    // ---- job decode ----
    const int b = blockIdx.x;
    int t, half, iters, k0;
    if (b < full_jobs) {            // full-K job
        t = b; half = -1; iters = K / BK; k0 = 0;
    } else {                        // half-K split job
        int s = b - full_jobs;
        t = full_jobs + (s >> 1);
        half = s & 1;
        iters = K / BK / 2;         // 32
        k0 = half * (K / 2);
    }
    int tbm, tbn;
    tile_coords(t, nbx, nby, tbm, tbn);
    const int bm = tbm * BM;
    const int bn = tbn * BN;

    const int wm_off = (wid >> 1) * 64;   // 0 or 64
    const int wn_off = (wid & 1) * 64;    // 0 or 64

    if (tid == 0) {
#pragma unroll
        for (int s = 0; s < STAGES; s++) {
            mbar_init(sb + SM_MBAR + s * 8, THREADS);        // full
            mbar_init(sb + SM_MBAR + 24 + s * 8, THREADS);   // empty
        }
    }
    __syncthreads();

    const __half* Ag = g_x + (size_t)bm * K;
    const __half* Bg = g_w + (size_t)bn * K;

    const int lr = tid >> 3;        // base row 0..15 (stride 16)
    const int lc = (tid & 7) * 8;   // element offset within 64-wide k-row

    auto fill_stage = [&](int stage, int kblk) {
        uint32_t a_s = sb_tiles + stage * STAGE_BYTES;
        uint32_t b_s = a_s + TILE_BYTES;
#pragma unroll
        for (int i = 0; i < 8; i++) {
            int r = lr + i * 16;
            cp16(a_s + sw128(r * 128 + lc * 2), Ag + (size_t)r * K + kblk + lc);
        }
#pragma unroll
        for (int i = 0; i < 8; i++) {
            int r = lr + i * 16;
            cp16(b_s + sw128(r * 128 + lc * 2), Bg + (size_t)r * K + kblk + lc);
        }
        cp_arrive_noinc(sb + SM_MBAR + stage * 8);
    };

    float acc[4][8][4];
#pragma unroll
    for (int mi = 0; mi < 4; mi++)
#pragma unroll
        for (int ni = 0; ni < 8; ni++)
#pragma unroll
            for (int e = 0; e < 4; e++) acc[mi][ni][e] = 0.0f;

    int p_stage = 0, p_phase = 1;   // producer (empty-waits)
    int c_stage = 0, c_phase = 0;   // consumer (full-waits)

    // Prologue: fill stages 0 and 1
#pragma unroll
    for (int itf = 0; itf < 2; itf++) {
        mbar_wait(sb + SM_MBAR + 24 + p_stage * 8, p_phase);
        fill_stage(p_stage, k0 + itf * BK);
        if (++p_stage == STAGES) { p_stage = 0; p_phase ^= 1; }
    }

    // ldmatrix lane addressing
    const int a_row_l = lane & 15;
    const int a_chk_l = lane >> 4;
    const int b_row_l = (lane & 7) + ((lane >> 4) << 3);
    const int b_chk_l = (lane >> 3) & 1;

    uint32_t afrag[2][4][4];
    uint32_t bfrag[2][4][4];

    for (int it = 0; it < iters; ++it) {
        mbar_wait(sb + SM_MBAR + c_stage * 8, c_phase);

        uint32_t a_s = sb_tiles + c_stage * STAGE_BYTES;
        uint32_t b_s = a_s + TILE_BYTES;

#pragma unroll
        for (int mi = 0; mi < 4; mi++) {
            int row = wm_off + mi * 16 + a_row_l;
            ldmx4(afrag[0][mi], a_s + sw128(row * 128 + a_chk_l * 16));
        }
#pragma unroll
        for (int nj = 0; nj < 4; nj++) {
            int row = wn_off + nj * 16 + b_row_l;
            ldmx4(bfrag[0][nj], b_s + sw128(row * 128 + b_chk_l * 16));
        }

#pragma unroll
        for (int ks = 0; ks < BK / 16; ks++) {
            const int cur = ks & 1;
            if (ks < BK / 16 - 1) {
                const int nxt = cur ^ 1;
#pragma unroll
                for (int mi = 0; mi < 4; mi++) {
                    int row = wm_off + mi * 16 + a_row_l;
                    ldmx4(afrag[nxt][mi],
                          a_s + sw128(row * 128 + (ks + 1) * 32 + a_chk_l * 16));
                }
#pragma unroll
                for (int nj = 0; nj < 4; nj++) {
                    int row = wn_off + nj * 16 + b_row_l;
                    ldmx4(bfrag[nxt][nj],
                          b_s + sw128(row * 128 + (ks + 1) * 32 + b_chk_l * 16));
                }
            }
#pragma unroll
            for (int mi = 0; mi < 4; mi++)
#pragma unroll
                for (int ni = 0; ni < 8; ni++)
                    mma16816(acc[mi][ni], afrag[cur][mi],
                             &bfrag[cur][ni >> 1][(ni & 1) * 2]);
        }

        mbar_arrive(sb + SM_MBAR + 24 + c_stage * 8);
        if (++c_stage == STAGES) { c_stage = 0; c_phase ^= 1; }

        if (it + 2 < iters) {
            mbar_wait(sb + SM_MBAR + 24 + p_stage * 8, p_phase);
            fill_stage(p_stage, k0 + (it + 2) * BK);
            if (++p_stage == STAGES) { p_stage = 0; p_phase ^= 1; }
        }
    }

    // Epilogue
    if (half < 0) {
        // Full job: C + bias, float2 stores
#pragma unroll
        for (int mi = 0; mi < 4; mi++) {
            int r0 = bm + wm_off + mi * 16 + (lane >> 2);
#pragma unroll
            for (int ni = 0; ni < 8; ni++) {
                int col  = wn_off + ni * 8 + (lane & 3) * 2;
                float b0 = __ldg(&bias[bn + col]);
                float b1 = __ldg(&bias[bn + col + 1]);
                float2 v0 = make_float2(acc[mi][ni][0] + b0, acc[mi][ni][1] + b1);
                float2 v1 = make_float2(acc[mi][ni][2] + b0, acc[mi][ni][3] + b1);
                *reinterpret_cast<float2*>(C + (size_t)r0 * N + bn + col) = v0;
                *reinterpret_cast<float2*>(C + (size_t)(r0 + 8) * N + bn + col) = v1;
            }
        }
    } else {
        // Split job: write partial tile (half 0 folds bias), local 128x128
        float* P = g_part + ((size_t)(t - full_jobs) * 2 + half) * (BM * BN);
#pragma unroll
        for (int mi = 0; mi < 4; mi++) {
            int r0 = wm_off + mi * 16 + (lane >> 2);
#pragma unroll
            for (int ni = 0; ni < 8; ni++) {
                int col  = wn_off + ni * 8 + (lane & 3) * 2;
                float b0 = 0.f, b1 = 0.f;
                if (half == 0) {
                    b0 = __ldg(&bias[bn + col]);
                    b1 = __ldg(&bias[bn + col + 1]);
                }
                float2 v0 = make_float2(acc[mi][ni][0] + b0, acc[mi][ni][1] + b1);
                float2 v1 = make_float2(acc[mi][ni][2] + b0, acc[mi][ni][3] + b1);
                *reinterpret_cast<float2*>(P + (size_t)r0 * BN + col) = v0;
                *reinterpret_cast<float2*>(P + (size_t)(r0 + 8) * BN + col) = v1;
            }
        }
    }
}

// ---------------------------------------------------------------------------
// Reduce: C[tile elems] = part[t][0] + part[t][1] for the split tiles.
// ---------------------------------------------------------------------------
__global__ void reduce_kernel(float* __restrict__ C, int N, int nbx, int nby,
                              int full_jobs, int nsplit) {
    int idx = blockIdx.x * blockDim.x + threadIdx.x;   // elem*4 granularity
    int total = nsplit * BM * BN / 4;
    if (idx >= total) return;
    int tl = idx / (BM * BN / 4);
    int e4 = idx - tl * (BM * BN / 4);
    int e  = e4 * 4;
    int row = e / BN, col = e - row * BN;

    int tbm, tbn;
    tile_coords(full_jobs + tl, nbx, nby, tbm, tbn);

    const float4* p0 = reinterpret_cast<const float4*>(
        g_part + ((size_t)tl * 2 + 0) * (BM * BN) + e);
    const float4* p1 = reinterpret_cast<const float4*>(
        g_part + ((size_t)tl * 2 + 1) * (BM * BN) + e);
    float4 a = *p0, b = *p1;
    float4 o = make_float4(a.x + b.x, a.y + b.y, a.z + b.z, a.w + b.w);
    *reinterpret_cast<float4*>(
        C + (size_t)(tbm * BM + row) * N + tbn * BN + col) = o;
}

// ---------------------------------------------------------------------------
// Launch
// ---------------------------------------------------------------------------
extern "C" void kernel_launch(void* const* d_in, const int* in_sizes, int n_in,
                              void* d_out, int out_size) {
    const float* x      = (const float*)d_in[0];
    const int*   q      = (const int*)  d_in[1];
    const float* scales = (const float*)d_in[2];
    const float* bias   = (const float*)d_in[3];
    float*       out    = (float*)d_out;

    const int O = in_sizes[3];                 // 4096
    const int K = in_sizes[1] / O;             // 4096
    const int M = in_sizes[0] / K;             // 4096
    const int N = O;

    int nx_chunks = (int)((size_t)M * K / 8);
    int nq_chunks = O * (K >> 3);
    int total = nx_chunks + nq_chunks;
    prep_kernel<<<(total + 255) / 256, 256>>>(x, q, scales, nx_chunks, O, K);

    const int nbx = N / BN, nby = M / BM;
    const int ntiles = nbx * nby;              // 1024
    int waves  = ntiles / SLOTS;               // 3
    int full_jobs = waves * SLOTS;             // 888
    int nsplit = ntiles - full_jobs;           // 136
    if (nsplit > MAX_NSPLIT) { full_jobs = ntiles; nsplit = 0; }  // safety
    int njobs = full_jobs + 2 * nsplit;        // 1160

    cudaFuncSetAttribute(gemm_mma_kernel,
                         cudaFuncAttributeMaxDynamicSharedMemorySize, SMEM_TOTAL);
    gemm_mma_kernel<<<njobs, THREADS, SMEM_TOTAL>>>(bias, out, M, N, K,
                                                    full_jobs, ntiles);

    if (nsplit > 0) {
        int relems = nsplit * BM * BN / 4;
        reduce_kernel<<<(relems + 255) / 256, 256>>>(out, N, nbx, nby,
                                                     full_jobs, nsplit);
    }
}